// round 1
// baseline (speedup 1.0000x reference)
#include <cuda_runtime.h>
#include <cuda_bf16.h>

// Workload: out[b,n,0:3] = (T_b @ [pos,1]).xyz / w ;  out[b,n,3:6] = normalize(R_b @ nrm)
// batch_indices input is unused by the reference output (dead input).
// Pure HBM stream: 192 MB in + 192 MB out. Strategy: 2 vertices per thread
// = 3x float4 load + 3x float4 store, perfectly coalesced.

__global__ __launch_bounds__(256)
void xform_pairs_kernel(const float4* __restrict__ vin,
                        const float*  __restrict__ transforms,
                        float4* __restrict__ vout,
                        int pairsPerBatch)
{
    int p = blockIdx.x * blockDim.x + threadIdx.x;
    int b = blockIdx.y;
    if (p >= pairsPerBatch) return;

    // Uniform per-block transform load (all threads same b) -> L1 broadcast
    const float* t = transforms + (size_t)b * 16;
    float T00 = t[0],  T01 = t[1],  T02 = t[2],  T03 = t[3];
    float T10 = t[4],  T11 = t[5],  T12 = t[6],  T13 = t[7];
    float T20 = t[8],  T21 = t[9],  T22 = t[10], T23 = t[11];
    float T30 = t[12], T31 = t[13], T32 = t[14], T33 = t[15];

    // Each batch is pairsPerBatch*3 float4s; each pair is 3 float4s.
    size_t base = (size_t)b * pairsPerBatch * 3 + (size_t)p * 3;

    float4 f0 = vin[base + 0];
    float4 f1 = vin[base + 1];
    float4 f2 = vin[base + 2];

    // vertex 0: pos = (f0.x, f0.y, f0.z), nrm = (f0.w, f1.x, f1.y)
    // vertex 1: pos = (f1.z, f1.w, f2.x), nrm = (f2.y, f2.z, f2.w)

    float o[12];

    #pragma unroll
    for (int v = 0; v < 2; v++) {
        float x, y, z, nx, ny, nz;
        if (v == 0) { x = f0.x; y = f0.y; z = f0.z; nx = f0.w; ny = f1.x; nz = f1.y; }
        else        { x = f1.z; y = f1.w; z = f2.x; nx = f2.y; ny = f2.z; nz = f2.w; }

        // position transform (homogeneous)
        float px = fmaf(T00, x, fmaf(T01, y, fmaf(T02, z, T03)));
        float py = fmaf(T10, x, fmaf(T11, y, fmaf(T12, z, T13)));
        float pz = fmaf(T20, x, fmaf(T21, y, fmaf(T22, z, T23)));
        float pw = fmaf(T30, x, fmaf(T31, y, fmaf(T32, z, T33)));
        float invw = 1.0f / pw;   // w == 1 by construction; exact
        px *= invw; py *= invw; pz *= invw;

        // normal transform (rotation-ish part only) + normalize
        float tx = fmaf(T00, nx, fmaf(T01, ny, T02 * nz));
        float ty = fmaf(T10, nx, fmaf(T11, ny, T12 * nz));
        float tz = fmaf(T20, nx, fmaf(T21, ny, T22 * nz));
        float d  = fmaf(tx, tx, fmaf(ty, ty, tz * tz));
        // 1/max(sqrt(d), 1e-8) == rsqrt(max(d, 1e-16))
        float inv = rsqrtf(fmaxf(d, 1e-16f));
        tx *= inv; ty *= inv; tz *= inv;

        o[v * 6 + 0] = px; o[v * 6 + 1] = py; o[v * 6 + 2] = pz;
        o[v * 6 + 3] = tx; o[v * 6 + 4] = ty; o[v * 6 + 5] = tz;
    }

    vout[base + 0] = make_float4(o[0], o[1],  o[2],  o[3]);
    vout[base + 1] = make_float4(o[4], o[5],  o[6],  o[7]);
    vout[base + 2] = make_float4(o[8], o[9],  o[10], o[11]);
}

// Tail handler for odd N (not expected here, but keeps the kernel general):
__global__ void xform_tail_kernel(const float* __restrict__ vin,
                                  const float* __restrict__ transforms,
                                  float* __restrict__ vout,
                                  int N, int B)
{
    int b = blockIdx.x * blockDim.x + threadIdx.x;
    if (b >= B) return;
    if (N % 2 == 0) return;
    const float* t = transforms + (size_t)b * 16;
    size_t off = ((size_t)b * N + (N - 1)) * 6;
    float x = vin[off+0], y = vin[off+1], z = vin[off+2];
    float nx = vin[off+3], ny = vin[off+4], nz = vin[off+5];
    float px = fmaf(t[0], x, fmaf(t[1], y, fmaf(t[2], z, t[3])));
    float py = fmaf(t[4], x, fmaf(t[5], y, fmaf(t[6], z, t[7])));
    float pz = fmaf(t[8], x, fmaf(t[9], y, fmaf(t[10], z, t[11])));
    float pw = fmaf(t[12], x, fmaf(t[13], y, fmaf(t[14], z, t[15])));
    float invw = 1.0f / pw;
    float tx = fmaf(t[0], nx, fmaf(t[1], ny, t[2] * nz));
    float ty = fmaf(t[4], nx, fmaf(t[5], ny, t[6] * nz));
    float tz = fmaf(t[8], nx, fmaf(t[9], ny, t[10] * nz));
    float d = fmaf(tx, tx, fmaf(ty, ty, tz * tz));
    float inv = rsqrtf(fmaxf(d, 1e-16f));
    vout[off+0] = px * invw; vout[off+1] = py * invw; vout[off+2] = pz * invw;
    vout[off+3] = tx * inv;  vout[off+4] = ty * inv;  vout[off+5] = tz * inv;
}

extern "C" void kernel_launch(void* const* d_in, const int* in_sizes, int n_in,
                              void* d_out, int out_size)
{
    const float* vertices   = (const float*)d_in[0];  // (B, N, 6) float32
    // d_in[1] = batch_indices (B, M, 3) int32 — unused by the reference output
    const float* transforms = (const float*)d_in[2];  // (B, 4, 4) float32

    int B = in_sizes[2] / 16;                 // 8
    long long totalVerts = (long long)in_sizes[0] / 6;
    int N = (int)(totalVerts / B);            // 1,000,000
    int pairsPerBatch = N / 2;                // 500,000

    dim3 block(256);
    dim3 grid((pairsPerBatch + 255) / 256, B);
    xform_pairs_kernel<<<grid, block>>>((const float4*)vertices, transforms,
                                        (float4*)d_out, pairsPerBatch);
    if (N % 2 != 0) {
        xform_tail_kernel<<<(B + 127) / 128, 128>>>(vertices, transforms,
                                                    (float*)d_out, N, B);
    }
}